// round 6
// baseline (speedup 1.0000x reference)
#include <cuda_runtime.h>
#include <cuda_fp16.h>
#include <cstdint>

#define HW     576
#define CIN    512
#define HD     64
#define NTOK   2304      // V_NUM * HW
#define NPAIR  16        // groups(2) * heads(8)
#define NB     8
#define QSCALE (0.125f * 1.4426950408889634f)   // hd^-0.5 * log2(e)

// Scratch (device globals: allocation-free rule). All fp16.
__device__ __align__(16) __half g_xt[NB * HW * CIN];     // x transposed [b][hw][c]
__device__ __align__(16) __half g_wq[3 * CIN * CIN];     // w_qkv [o][c]
__device__ __align__(16) __half g_wp[CIN * CIN];         // w_proj [o][c]
__device__ __align__(16) __half g_q[NPAIR * NTOK * HD];  // [p][n][d], scale folded
__device__ __align__(16) __half g_k[NPAIR * NTOK * HD];  // [p][n][d]
__device__ __align__(16) __half g_v[NPAIR * HD * NTOK];  // [p][d][n]
__device__ __align__(16) __half g_ao[NB * HW * CIN];     // attn out [b][hw][c]

// ---------------- helpers ----------------
__device__ __forceinline__ void mma16(float* c, const uint32_t* a, uint32_t b0, uint32_t b1) {
    asm("mma.sync.aligned.m16n8k16.row.col.f32.f16.f16.f32 "
        "{%0,%1,%2,%3}, {%4,%5,%6,%7}, {%8,%9}, {%0,%1,%2,%3};\n"
        : "+f"(c[0]), "+f"(c[1]), "+f"(c[2]), "+f"(c[3])
        : "r"(a[0]), "r"(a[1]), "r"(a[2]), "r"(a[3]), "r"(b0), "r"(b1));
}
__device__ __forceinline__ void ldsm4(uint32_t* d, uint32_t a) {
    asm volatile("ldmatrix.sync.aligned.m8n8.x4.shared.b16 {%0,%1,%2,%3}, [%4];\n"
        : "=r"(d[0]), "=r"(d[1]), "=r"(d[2]), "=r"(d[3]) : "r"(a));
}
__device__ __forceinline__ uint32_t s2u(const void* p) {
    return (uint32_t)__cvta_generic_to_shared(p);
}
__device__ __forceinline__ void cpa16(uint32_t dst, const void* src) {
    asm volatile("cp.async.cg.shared.global [%0], [%1], 16;\n" :: "r"(dst), "l"(src));
}
__device__ __forceinline__ void cpcommit() {
    asm volatile("cp.async.commit_group;\n" ::: "memory");
}
#define CPWAIT(n) asm volatile("cp.async.wait_group %0;\n" :: "n"(n) : "memory")

// fp16 LDSM lane offsets (bytes). strideB = row stride in bytes.
// A m16k16: matrices {r0-7,klo}{r8-15,klo}{r0-7,khi}{r8-15,khi}
__device__ __forceinline__ uint32_t a_off16(int lane, int strideB) {
    return (uint32_t)(((lane & 7) + ((lane >> 3) & 1) * 8) * strideB + (lane >> 4) * 16);
}
// B (rows [n][k]) x4: {n0-7,klo}{n0-7,khi}{n8-15,klo}{n8-15,khi}
__device__ __forceinline__ uint32_t b_off16(int lane, int strideB) {
    return (uint32_t)(((lane & 7) + ((lane >> 4) & 1) * 8) * strideB + ((lane >> 3) & 1) * 16);
}

#define STRB 144      // 72 halves per smem row

// ---------------------------------------------------------------------------
// Prologue 1: convert weights to fp16.
// ---------------------------------------------------------------------------
__global__ __launch_bounds__(256) void cvt_w(const float4* __restrict__ wq,
                                             const float4* __restrict__ wp) {
    int i = blockIdx.x * 256 + threadIdx.x;     // 262144 float4s
    float4 v; __half* dst;
    if (i < 196608) { v = wq[i];          dst = g_wq + i * 4; }
    else            { v = wp[i - 196608]; dst = g_wp + (i - 196608) * 4; }
    *(__half2*)dst       = __floats2half2_rn(v.x, v.y);
    *(__half2*)(dst + 2) = __floats2half2_rn(v.z, v.w);
}

// ---------------------------------------------------------------------------
// Prologue 2: transpose+convert x [b][c][hw] -> g_xt [b][hw][c] fp16.
// grid (9 hw-tiles, 8 c-tiles, 8 b), 256 thr, 64x64 tiles.
// ---------------------------------------------------------------------------
__global__ __launch_bounds__(256) void tr_x(const float* __restrict__ x) {
    __shared__ float sT[64 * 65];
    const int tid = threadIdx.x;
    const int hw0 = blockIdx.x * 64, c0 = blockIdx.y * 64, b = blockIdx.z;
#pragma unroll
    for (int rr = 0; rr < 4; rr++) {
        int f = tid + rr * 256, row = f >> 4, h4 = (f & 15) * 4;
        float4 v = *(const float4*)&x[((b * CIN) + c0 + row) * HW + hw0 + h4];
        sT[row * 65 + h4 + 0] = v.x; sT[row * 65 + h4 + 1] = v.y;
        sT[row * 65 + h4 + 2] = v.z; sT[row * 65 + h4 + 3] = v.w;
    }
    __syncthreads();
    // 256 work items: 64 hw-rows x 4 chunks of 16 channels (one pass)
    {
        int f = tid, hwr = f >> 2, cc = (f & 3) * 16;
        __half* dst = g_xt + ((b * HW) + hw0 + hwr) * CIN + c0 + cc;
#pragma unroll
        for (int j = 0; j < 8; j++)
            *(__half2*)(dst + 2 * j) =
                __floats2half2_rn(sT[(cc + 2 * j) * 65 + hwr], sT[(cc + 2 * j + 1) * 65 + hwr]);
    }
}

// ---------------------------------------------------------------------------
// Kernel A: QKV. D[m=hw 64][n=o 128] = X[hw][c] @ W[o][c]^T, K=512, BK=64.
// 8 warps (2M x 4N, warp m32 x n32). 2-stage cp.async, 1 sync/iter.
// ---------------------------------------------------------------------------
__global__ __launch_bounds__(256, 3) void qkv_mma() {
    extern __shared__ __half smh[];
    const uint32_t sXb = s2u(smh);
    const uint32_t sWb = sXb + 2 * 4608 * 2;
    const int tid = threadIdx.x, wp = tid >> 5, lane = tid & 31;
    const int r = lane >> 2, q = lane & 3;
    const int wm = wp >> 2, wn = wp & 3;
    const int hw0 = blockIdx.x * 64, o0 = blockIdx.y * 128, b = blockIdx.z;
    const uint32_t aof = a_off16(lane, STRB), bof = b_off16(lane, STRB);

#define QKV_PF(K0, BUF) {                                                       \
    _Pragma("unroll") for (int rr = 0; rr < 2; rr++) {                          \
        int f = tid + rr * 256, row = f >> 3, ch = (f & 7) * 8;                 \
        cpa16(sXb + (uint32_t)((BUF) * 4608 + row * 72 + ch) * 2u,              \
              g_xt + ((b * HW) + hw0 + row) * CIN + (K0) + ch);                 \
    }                                                                           \
    _Pragma("unroll") for (int rr = 0; rr < 4; rr++) {                          \
        int f = tid + rr * 256, row = f >> 3, ch = (f & 7) * 8;                 \
        cpa16(sWb + (uint32_t)((BUF) * 9216 + row * 72 + ch) * 2u,              \
              g_wq + (o0 + row) * CIN + (K0) + ch);                             \
    }                                                                           \
    cpcommit(); }

    QKV_PF(0, 0);
    float acc[2][4][4] = {};

    for (int kk = 0; kk < 8; kk++) {
        const int buf = kk & 1;
        CPWAIT(0);
        __syncthreads();
        if (kk + 1 < 8) QKV_PF((kk + 1) * 64, buf ^ 1);

        const uint32_t xa = sXb + (uint32_t)(buf * 4608 + wm * 32 * 72) * 2u + aof;
        const uint32_t wa = sWb + (uint32_t)(buf * 9216 + wn * 32 * 72) * 2u + bof;
#pragma unroll
        for (int s = 0; s < 4; s++) {
            uint32_t aX[2][4];
            ldsm4(aX[0], xa + s * 32);
            ldsm4(aX[1], xa + 16 * STRB + s * 32);
#pragma unroll
            for (int j2 = 0; j2 < 2; j2++) {
                uint32_t bb[4]; ldsm4(bb, wa + j2 * 16 * STRB + s * 32);
#pragma unroll
                for (int mi = 0; mi < 2; mi++) {
                    mma16(acc[mi][j2 * 2],     aX[mi], bb[0], bb[1]);
                    mma16(acc[mi][j2 * 2 + 1], aX[mi], bb[2], bb[3]);
                }
            }
        }
    }

    // scatter epilogue: o = head*192 + which*64 + d ; token n = v*HW + hw
    const int g2 = b >> 2, vv = b & 3;
#pragma unroll
    for (int mi = 0; mi < 2; mi++) {
        int hwr = hw0 + wm * 32 + mi * 16 + r;
        int n0t = vv * HW + hwr, n1t = n0t + 8;
#pragma unroll
        for (int nj = 0; nj < 4; nj++) {
            int o = o0 + wn * 32 + nj * 8 + 2 * q;
            int head = o / 192, rem = o - head * 192, which = rem >> 6, d = rem & 63;
            int pp = g2 * 8 + head;
            float c0 = acc[mi][nj][0], c1 = acc[mi][nj][1];
            float c2 = acc[mi][nj][2], c3 = acc[mi][nj][3];
            if (which == 0) {
                *(__half2*)&g_q[(pp * NTOK + n0t) * HD + d] = __floats2half2_rn(c0 * QSCALE, c1 * QSCALE);
                *(__half2*)&g_q[(pp * NTOK + n1t) * HD + d] = __floats2half2_rn(c2 * QSCALE, c3 * QSCALE);
            } else if (which == 1) {
                *(__half2*)&g_k[(pp * NTOK + n0t) * HD + d] = __floats2half2_rn(c0, c1);
                *(__half2*)&g_k[(pp * NTOK + n1t) * HD + d] = __floats2half2_rn(c2, c3);
            } else {
                g_v[(pp * HD + d) * NTOK + n0t]     = __float2half_rn(c0);
                g_v[(pp * HD + d + 1) * NTOK + n0t] = __float2half_rn(c1);
                g_v[(pp * HD + d) * NTOK + n1t]     = __float2half_rn(c2);
                g_v[(pp * HD + d + 1) * NTOK + n1t] = __float2half_rn(c3);
            }
        }
    }
}

// ---------------------------------------------------------------------------
// Kernel B: flash attention fp16, register-resident P, f16x2 exp2.
// grid (18, 16), 256 thr (8 warps x m16 strips), BM=128, BN=64, 3-stage ring.
// smem: sQ [128][72]h (staging) | sK 3x[64][72]h | sV 3x[64][72]h.
// ---------------------------------------------------------------------------
__global__ __launch_bounds__(256, 2) void flash_mma() {
    extern __shared__ __half smh[];
    const uint32_t sQb = s2u(smh);
    const uint32_t sKb = sQb + 128 * 72 * 2;
    const uint32_t sVb = sKb + 3 * 4608 * 2;

    const int tid = threadIdx.x, wp = tid >> 5, lane = tid & 31;
    const int r = lane >> 2, q = lane & 3, w16 = wp * 16;
    const int p = blockIdx.y, m0 = blockIdx.x * 128;

    const __half* Qb = g_q + (p * NTOK + m0) * HD;
    const __half* Kb = g_k + p * NTOK * HD;
    const __half* Vb = g_v + p * HD * NTOK;

    const uint32_t aof = a_off16(lane, STRB), bof = b_off16(lane, STRB);

#define FL_PF(N0, BUF) {                                                        \
    _Pragma("unroll") for (int rr = 0; rr < 2; rr++) {                          \
        int f = tid + rr * 256, row = f >> 3, ch = (f & 7) * 8;                 \
        cpa16(sKb + (uint32_t)((BUF) * 4608 + row * 72 + ch) * 2u,              \
              Kb + ((N0) + row) * HD + ch);                                     \
        cpa16(sVb + (uint32_t)((BUF) * 4608 + row * 72 + ch) * 2u,              \
              Vb + row * NTOK + (N0) + ch);                                     \
    }                                                                           \
    cpcommit(); }

    // stage Q, then first two K/V stages
#pragma unroll
    for (int rr = 0; rr < 4; rr++) {
        int f = tid + rr * 256, row = f >> 3, ch = (f & 7) * 8;
        cpa16(sQb + (uint32_t)(row * 72 + ch) * 2u, Qb + row * HD + ch);
    }
    cpcommit();
    FL_PF(0, 0);
    FL_PF(64, 1);

    CPWAIT(1);            // Q + stage0 ready
    __syncthreads();
    uint32_t qf[4][4];
    {
        const uint32_t qa = sQb + (uint32_t)(w16 * 72) * 2u + aof;
#pragma unroll
        for (int s = 0; s < 4; s++) ldsm4(qf[s], qa + s * 32);
    }

    float rO[8][4] = {};
    float l0 = 0.f, l1 = 0.f;

    for (int it = 0; it < 36; it++) {
        const int buf = it % 3;
        if (it) { CPWAIT(1); __syncthreads(); }
        if (it + 2 < 36) FL_PF((it + 2) * 64, (it + 2) % 3);

        // S(m16 x n64) = Q K^T  (base-2 scale folded into Q)
        float S[8][4] = {};
        {
            const uint32_t ka = sKb + (uint32_t)(buf * 4608) * 2u + bof;
#pragma unroll
            for (int s = 0; s < 4; s++)
#pragma unroll
                for (int j = 0; j < 4; j++) {
                    uint32_t bb[4]; ldsm4(bb, ka + (uint32_t)(j * 16 * STRB) + s * 32);
                    mma16(S[2 * j],     qf[s], bb[0], bb[1]);
                    mma16(S[2 * j + 1], qf[s], bb[2], bb[3]);
                }
        }

        // softmax: p = exp2(S) in fp16x2, P fragments built in registers.
        // S acc (n-tile nt): c0,c1=row r; c2,c3=row r+8 at cols nt*8+2q.
        // A-frag (k-tile t): a0=row r k=2q(tile 2t), a1=row r+8 (2t),
        //                    a2=row r (2t+1), a3=row r+8 (2t+1).
        uint32_t pf[4][4];
        float sum0 = 0.f, sum1 = 0.f;
#pragma unroll
        for (int t = 0; t < 4; t++) {
#pragma unroll
            for (int u = 0; u < 2; u++) {
                const float* Sv = S[2 * t + u];
                __half2 e01 = h2exp2(__floats2half2_rn(Sv[0], Sv[1]));
                __half2 e23 = h2exp2(__floats2half2_rn(Sv[2], Sv[3]));
                pf[t][2 * u]     = *(uint32_t*)&e01;   // row r
                pf[t][2 * u + 1] = *(uint32_t*)&e23;   // row r+8
                float2 f01 = __half22float2(e01);
                float2 f23 = __half22float2(e23);
                sum0 += f01.x + f01.y;
                sum1 += f23.x + f23.y;
            }
        }
        sum0 += __shfl_xor_sync(0xffffffffu, sum0, 1);
        sum0 += __shfl_xor_sync(0xffffffffu, sum0, 2);
        sum1 += __shfl_xor_sync(0xffffffffu, sum1, 1);
        sum1 += __shfl_xor_sync(0xffffffffu, sum1, 2);
        l0 += sum0; l1 += sum1;

        // O(m16 x d64) += P @ V   (P fragments from registers)
        {
            const uint32_t va = sVb + (uint32_t)(buf * 4608) * 2u + bof;
#pragma unroll
            for (int t = 0; t < 4; t++)
#pragma unroll
                for (int j = 0; j < 4; j++) {
                    uint32_t bb[4]; ldsm4(bb, va + (uint32_t)(j * 16 * STRB) + t * 32);
                    mma16(rO[2 * j],     pf[t], bb[0], bb[1]);
                    mma16(rO[2 * j + 1], pf[t], bb[2], bb[3]);
                }
        }
    }

    // epilogue: normalize, write g_ao [b][hw][c] fp16
    const float i0 = 1.f / l0, i1 = 1.f / l1;
    const int head = p & 7, gi = p >> 3;
    const int row0 = m0 + w16 + r, row1 = row0 + 8;
    const int v0 = row0 / HW, v1 = row1 / HW;
    __half* o0p = g_ao + ((gi * 4 + v0) * HW + (row0 - v0 * HW)) * CIN + head * 64;
    __half* o1p = g_ao + ((gi * 4 + v1) * HW + (row1 - v1 * HW)) * CIN + head * 64;
#pragma unroll
    for (int dt = 0; dt < 8; dt++) {
        *(__half2*)&o0p[dt * 8 + 2 * q] = __floats2half2_rn(rO[dt][0] * i0, rO[dt][1] * i0);
        *(__half2*)&o1p[dt * 8 + 2 * q] = __floats2half2_rn(rO[dt][2] * i1, rO[dt][3] * i1);
    }
}

// ---------------------------------------------------------------------------
// Kernel C: proj + bias. D[m=o 128][n=hw 64] = W[o][c] @ AO[hw][c]^T.
// 8 warps (4M x 2N, warp m32 x n32). 2-stage, 1 sync/iter. Output fp32.
// ---------------------------------------------------------------------------
__global__ __launch_bounds__(256, 3) void proj_mma(const float* __restrict__ bias,
                                                   float* __restrict__ out) {
    extern __shared__ __half smh[];
    const uint32_t sWb = s2u(smh);
    const uint32_t sBb = sWb + 2 * 9216 * 2;
    const int tid = threadIdx.x, wp = tid >> 5, lane = tid & 31;
    const int r = lane >> 2, q = lane & 3;
    const int wm = wp >> 1, wn = wp & 1;
    const int o0 = blockIdx.x * 128, hw0 = blockIdx.y * 64, b = blockIdx.z;
    const uint32_t aof = a_off16(lane, STRB), bof = b_off16(lane, STRB);

#define PRJ_PF(K0, BUF) {                                                       \
    _Pragma("unroll") for (int rr = 0; rr < 4; rr++) {                          \
        int f = tid + rr * 256, row = f >> 3, ch = (f & 7) * 8;                 \
        cpa16(sWb + (uint32_t)((BUF) * 9216 + row * 72 + ch) * 2u,              \
              g_wp + (o0 + row) * CIN + (K0) + ch);                             \
    }                                                                           \
    _Pragma("unroll") for (int rr = 0; rr < 2; rr++) {                          \
        int f = tid + rr * 256, row = f >> 3, ch = (f & 7) * 8;                 \
        cpa16(sBb + (uint32_t)((BUF) * 4608 + row * 72 + ch) * 2u,              \
              g_ao + ((b * HW) + hw0 + row) * CIN + (K0) + ch);                 \
    }                                                                           \
    cpcommit(); }

    PRJ_PF(0, 0);
    float acc[2][4][4] = {};

    for (int kk = 0; kk < 8; kk++) {
        const int buf = kk & 1;
        CPWAIT(0);
        __syncthreads();
        if (kk + 1 < 8) PRJ_PF((kk + 1) * 64, buf ^ 1);

        const uint32_t wa = sWb + (uint32_t)(buf * 9216 + wm * 32 * 72) * 2u + aof;
        const uint32_t xa = sBb + (uint32_t)(buf * 4608 + wn * 32 * 72) * 2u + bof;
#pragma unroll
        for (int s = 0; s < 4; s++) {
            uint32_t aW[2][4];
            ldsm4(aW[0], wa + s * 32);
            ldsm4(aW[1], wa + 16 * STRB + s * 32);
#pragma unroll
            for (int j2 = 0; j2 < 2; j2++) {
                uint32_t bb[4]; ldsm4(bb, xa + j2 * 16 * STRB + s * 32);
#pragma unroll
                for (int mi = 0; mi < 2; mi++) {
                    mma16(acc[mi][j2 * 2],     aW[mi], bb[0], bb[1]);
                    mma16(acc[mi][j2 * 2 + 1], aW[mi], bb[2], bb[3]);
                }
            }
        }
    }

#pragma unroll
    for (int mi = 0; mi < 2; mi++) {
        int o_r = o0 + wm * 32 + mi * 16 + r;
        float bv0 = bias[o_r], bv1 = bias[o_r + 8];
#pragma unroll
        for (int nj = 0; nj < 4; nj++) {
            int hw = hw0 + wn * 32 + nj * 8 + 2 * q;
            *(float2*)&out[(b * CIN + o_r) * HW + hw] =
                make_float2(acc[mi][nj][0] + bv0, acc[mi][nj][1] + bv0);
            *(float2*)&out[(b * CIN + o_r + 8) * HW + hw] =
                make_float2(acc[mi][nj][2] + bv1, acc[mi][nj][3] + bv1);
        }
    }
}

// ---------------------------------------------------------------------------
extern "C" void kernel_launch(void* const* d_in, const int* in_sizes, int n_in,
                              void* d_out, int out_size) {
    const float* x      = (const float*)d_in[0];
    const float* w_qkv  = (const float*)d_in[1];
    const float* w_proj = (const float*)d_in[2];
    const float* b_proj = (const float*)d_in[3];
    float* out = (float*)d_out;

    cudaFuncSetAttribute(qkv_mma,   cudaFuncAttributeMaxDynamicSharedMemorySize, 55296);
    cudaFuncSetAttribute(flash_mma, cudaFuncAttributeMaxDynamicSharedMemorySize, 73728);
    cudaFuncSetAttribute(proj_mma,  cudaFuncAttributeMaxDynamicSharedMemorySize, 55296);

    cvt_w<<<1024, 256>>>((const float4*)w_qkv, (const float4*)w_proj);
    tr_x<<<dim3(9, 8, 8), 256>>>(x);
    qkv_mma<<<dim3(9, 12, 8), 256, 55296>>>();
    flash_mma<<<dim3(18, 16), 256, 73728>>>();
    proj_mma<<<dim3(4, 9, 8), 256, 55296>>>(b_proj, out);
}

// round 7
// speedup vs baseline: 1.3971x; 1.3971x over previous
#include <cuda_runtime.h>
#include <cuda_fp16.h>
#include <cstdint>

#define HW     576
#define CIN    512
#define HD     64
#define NTOK   2304      // V_NUM * HW
#define NPAIR  16        // groups(2) * heads(8)
#define NB     8
#define QSCALE (0.125f * 1.4426950408889634f)   // hd^-0.5 * log2(e)
#define ONES   0x3C003C00u                       // half2(1.0, 1.0)

// Scratch (device globals: allocation-free rule). All fp16.
__device__ __align__(16) __half g_xt[NB * HW * CIN];     // x transposed [b][hw][c]
__device__ __align__(16) __half g_wq[3 * CIN * CIN];     // w_qkv [o][c]
__device__ __align__(16) __half g_wp[CIN * CIN];         // w_proj [o][c]
__device__ __align__(16) __half g_q[NPAIR * NTOK * HD];  // [p][n][d], scale folded
__device__ __align__(16) __half g_k[NPAIR * NTOK * HD];  // [p][n][d]
__device__ __align__(16) __half g_v[NPAIR * HD * NTOK];  // [p][d][n]
__device__ __align__(16) __half g_ao[NB * HW * CIN];     // attn out [b][hw][c]

// ---------------- helpers ----------------
__device__ __forceinline__ void mma16(float* c, const uint32_t* a, uint32_t b0, uint32_t b1) {
    asm("mma.sync.aligned.m16n8k16.row.col.f32.f16.f16.f32 "
        "{%0,%1,%2,%3}, {%4,%5,%6,%7}, {%8,%9}, {%0,%1,%2,%3};\n"
        : "+f"(c[0]), "+f"(c[1]), "+f"(c[2]), "+f"(c[3])
        : "r"(a[0]), "r"(a[1]), "r"(a[2]), "r"(a[3]), "r"(b0), "r"(b1));
}
__device__ __forceinline__ void ldsm4(uint32_t* d, uint32_t a) {
    asm volatile("ldmatrix.sync.aligned.m8n8.x4.shared.b16 {%0,%1,%2,%3}, [%4];\n"
        : "=r"(d[0]), "=r"(d[1]), "=r"(d[2]), "=r"(d[3]) : "r"(a));
}
__device__ __forceinline__ uint32_t s2u(const void* p) {
    return (uint32_t)__cvta_generic_to_shared(p);
}
__device__ __forceinline__ void cpa16(uint32_t dst, const void* src) {
    asm volatile("cp.async.cg.shared.global [%0], [%1], 16;\n" :: "r"(dst), "l"(src));
}
__device__ __forceinline__ void cpcommit() {
    asm volatile("cp.async.commit_group;\n" ::: "memory");
}
#define CPWAIT(n) asm volatile("cp.async.wait_group %0;\n" :: "n"(n) : "memory")

// fp16 LDSM lane offsets (bytes). strideB = row stride in bytes.
__device__ __forceinline__ uint32_t a_off16(int lane, int strideB) {
    return (uint32_t)(((lane & 7) + ((lane >> 3) & 1) * 8) * strideB + (lane >> 4) * 16);
}
__device__ __forceinline__ uint32_t b_off16(int lane, int strideB) {
    return (uint32_t)(((lane & 7) + ((lane >> 4) & 1) * 8) * strideB + ((lane >> 3) & 1) * 16);
}

#define STRB 144      // 72 halves per smem row

// ---------------------------------------------------------------------------
// Prologue 1: convert weights to fp16.
// ---------------------------------------------------------------------------
__global__ __launch_bounds__(256) void cvt_w(const float4* __restrict__ wq,
                                             const float4* __restrict__ wp) {
    int i = blockIdx.x * 256 + threadIdx.x;
    float4 v; __half* dst;
    if (i < 196608) { v = wq[i];          dst = g_wq + i * 4; }
    else            { v = wp[i - 196608]; dst = g_wp + (i - 196608) * 4; }
    *(__half2*)dst       = __floats2half2_rn(v.x, v.y);
    *(__half2*)(dst + 2) = __floats2half2_rn(v.z, v.w);
}

// ---------------------------------------------------------------------------
// Prologue 2: transpose+convert x [b][c][hw] -> g_xt [b][hw][c] fp16.
// ---------------------------------------------------------------------------
__global__ __launch_bounds__(256) void tr_x(const float* __restrict__ x) {
    __shared__ float sT[64 * 65];
    const int tid = threadIdx.x;
    const int hw0 = blockIdx.x * 64, c0 = blockIdx.y * 64, b = blockIdx.z;
#pragma unroll
    for (int rr = 0; rr < 4; rr++) {
        int f = tid + rr * 256, row = f >> 4, h4 = (f & 15) * 4;
        float4 v = *(const float4*)&x[((b * CIN) + c0 + row) * HW + hw0 + h4];
        sT[row * 65 + h4 + 0] = v.x; sT[row * 65 + h4 + 1] = v.y;
        sT[row * 65 + h4 + 2] = v.z; sT[row * 65 + h4 + 3] = v.w;
    }
    __syncthreads();
    {
        int f = tid, hwr = f >> 2, cc = (f & 3) * 16;
        __half* dst = g_xt + ((b * HW) + hw0 + hwr) * CIN + c0 + cc;
#pragma unroll
        for (int j = 0; j < 8; j++)
            *(__half2*)(dst + 2 * j) =
                __floats2half2_rn(sT[(cc + 2 * j) * 65 + hwr], sT[(cc + 2 * j + 1) * 65 + hwr]);
    }
}

// ---------------------------------------------------------------------------
// Kernel A: QKV. D[m=hw 64][n=o 128] = X[hw][c] @ W[o][c]^T, K=512, BK=64.
// ---------------------------------------------------------------------------
__global__ __launch_bounds__(256, 3) void qkv_mma() {
    extern __shared__ __half smh[];
    const uint32_t sXb = s2u(smh);
    const uint32_t sWb = sXb + 2 * 4608 * 2;
    const int tid = threadIdx.x, wp = tid >> 5, lane = tid & 31;
    const int r = lane >> 2, q = lane & 3;
    const int wm = wp >> 2, wn = wp & 3;
    const int hw0 = blockIdx.x * 64, o0 = blockIdx.y * 128, b = blockIdx.z;
    const uint32_t aof = a_off16(lane, STRB), bof = b_off16(lane, STRB);

#define QKV_PF(K0, BUF) {                                                       \
    _Pragma("unroll") for (int rr = 0; rr < 2; rr++) {                          \
        int f = tid + rr * 256, row = f >> 3, ch = (f & 7) * 8;                 \
        cpa16(sXb + (uint32_t)((BUF) * 4608 + row * 72 + ch) * 2u,              \
              g_xt + ((b * HW) + hw0 + row) * CIN + (K0) + ch);                 \
    }                                                                           \
    _Pragma("unroll") for (int rr = 0; rr < 4; rr++) {                          \
        int f = tid + rr * 256, row = f >> 3, ch = (f & 7) * 8;                 \
        cpa16(sWb + (uint32_t)((BUF) * 9216 + row * 72 + ch) * 2u,              \
              g_wq + (o0 + row) * CIN + (K0) + ch);                             \
    }                                                                           \
    cpcommit(); }

    QKV_PF(0, 0);
    float acc[2][4][4] = {};

    for (int kk = 0; kk < 8; kk++) {
        const int buf = kk & 1;
        CPWAIT(0);
        __syncthreads();
        if (kk + 1 < 8) QKV_PF((kk + 1) * 64, buf ^ 1);

        const uint32_t xa = sXb + (uint32_t)(buf * 4608 + wm * 32 * 72) * 2u + aof;
        const uint32_t wa = sWb + (uint32_t)(buf * 9216 + wn * 32 * 72) * 2u + bof;
#pragma unroll
        for (int s = 0; s < 4; s++) {
            uint32_t aX[2][4];
            ldsm4(aX[0], xa + s * 32);
            ldsm4(aX[1], xa + 16 * STRB + s * 32);
#pragma unroll
            for (int j2 = 0; j2 < 2; j2++) {
                uint32_t bb[4]; ldsm4(bb, wa + j2 * 16 * STRB + s * 32);
#pragma unroll
                for (int mi = 0; mi < 2; mi++) {
                    mma16(acc[mi][j2 * 2],     aX[mi], bb[0], bb[1]);
                    mma16(acc[mi][j2 * 2 + 1], aX[mi], bb[2], bb[3]);
                }
            }
        }
    }

    const int g2 = b >> 2, vv = b & 3;
#pragma unroll
    for (int mi = 0; mi < 2; mi++) {
        int hwr = hw0 + wm * 32 + mi * 16 + r;
        int n0t = vv * HW + hwr, n1t = n0t + 8;
#pragma unroll
        for (int nj = 0; nj < 4; nj++) {
            int o = o0 + wn * 32 + nj * 8 + 2 * q;
            int head = o / 192, rem = o - head * 192, which = rem >> 6, d = rem & 63;
            int pp = g2 * 8 + head;
            float c0 = acc[mi][nj][0], c1 = acc[mi][nj][1];
            float c2 = acc[mi][nj][2], c3 = acc[mi][nj][3];
            if (which == 0) {
                *(__half2*)&g_q[(pp * NTOK + n0t) * HD + d] = __floats2half2_rn(c0 * QSCALE, c1 * QSCALE);
                *(__half2*)&g_q[(pp * NTOK + n1t) * HD + d] = __floats2half2_rn(c2 * QSCALE, c3 * QSCALE);
            } else if (which == 1) {
                *(__half2*)&g_k[(pp * NTOK + n0t) * HD + d] = __floats2half2_rn(c0, c1);
                *(__half2*)&g_k[(pp * NTOK + n1t) * HD + d] = __floats2half2_rn(c2, c3);
            } else {
                g_v[(pp * HD + d) * NTOK + n0t]     = __float2half_rn(c0);
                g_v[(pp * HD + d + 1) * NTOK + n0t] = __float2half_rn(c1);
                g_v[(pp * HD + d) * NTOK + n1t]     = __float2half_rn(c2);
                g_v[(pp * HD + d + 1) * NTOK + n1t] = __float2half_rn(c3);
            }
        }
    }
}

// ---------------------------------------------------------------------------
// Kernel B: flash attention fp16, FA2-style: 4 warps x m32 strips, BM=128.
// n processed in two 32-halves; P register-resident; row sums via ones-mma.
// grid (18, 16), 128 thr, 3-stage cp.async ring.
// smem: sQ [128][72]h | sK 3x[64][72]h | sV 3x[64][72]h = 73728 B.
// ---------------------------------------------------------------------------
__global__ __launch_bounds__(128, 2) void flash_mma() {
    extern __shared__ __half smh[];
    const uint32_t sQb = s2u(smh);
    const uint32_t sKb = sQb + 128 * 72 * 2;
    const uint32_t sVb = sKb + 3 * 4608 * 2;

    const int tid = threadIdx.x, wm = tid >> 5, lane = tid & 31;
    const int r = lane >> 2, q = lane & 3;
    const int p = blockIdx.y, m0 = blockIdx.x * 128;

    const __half* Qb = g_q + (p * NTOK + m0) * HD;
    const __half* Kb = g_k + p * NTOK * HD;
    const __half* Vb = g_v + p * HD * NTOK;

    const uint32_t aof = a_off16(lane, STRB), bof = b_off16(lane, STRB);

#define FL_PF(N0, BUF) {                                                        \
    _Pragma("unroll") for (int rr = 0; rr < 4; rr++) {                          \
        int f = tid + rr * 128, row = f >> 3, ch = (f & 7) * 8;                 \
        cpa16(sKb + (uint32_t)((BUF) * 4608 + row * 72 + ch) * 2u,              \
              Kb + ((N0) + row) * HD + ch);                                     \
        cpa16(sVb + (uint32_t)((BUF) * 4608 + row * 72 + ch) * 2u,              \
              Vb + row * NTOK + (N0) + ch);                                     \
    }                                                                           \
    cpcommit(); }

    // stage Q (128 rows x 64 halves), then first two K/V stages
#pragma unroll
    for (int rr = 0; rr < 8; rr++) {
        int f = tid + rr * 128, row = f >> 3, ch = (f & 7) * 8;
        cpa16(sQb + (uint32_t)(row * 72 + ch) * 2u, Qb + row * HD + ch);
    }
    cpcommit();
    FL_PF(0, 0);
    FL_PF(64, 1);

    CPWAIT(1);            // Q + stage0 ready
    __syncthreads();
    uint32_t qf[2][4][4];
#pragma unroll
    for (int st = 0; st < 2; st++) {
        const uint32_t qa = sQb + (uint32_t)((wm * 32 + st * 16) * 72) * 2u + aof;
#pragma unroll
        for (int s = 0; s < 4; s++) ldsm4(qf[st][s], qa + s * 32);
    }

    float rO[2][8][4] = {};     // [strip][d-tile][4]
    float lacc[2][4] = {};      // row sums via ones-mma (fp32 acc)

    for (int it = 0; it < 36; it++) {
        const int buf = it % 3;
        if (it) { CPWAIT(1); __syncthreads(); }
        if (it + 2 < 36) FL_PF((it + 2) * 64, (it + 2) % 3);

        const uint32_t ka = sKb + (uint32_t)(buf * 4608) * 2u + bof;
        const uint32_t va = sVb + (uint32_t)(buf * 4608) * 2u + bof;

#pragma unroll
        for (int h = 0; h < 2; h++) {     // n in two 32-halves
            // S(m32 x n32) = Q K^T (base-2 scale folded into Q)
            float S[2][4][4] = {};
#pragma unroll
            for (int s = 0; s < 4; s++)
#pragma unroll
                for (int jn = 0; jn < 2; jn++) {
                    uint32_t bb[4];
                    ldsm4(bb, ka + (uint32_t)((h * 32 + jn * 16) * STRB) + s * 32);
#pragma unroll
                    for (int st = 0; st < 2; st++) {
                        mma16(S[st][jn * 2],     qf[st][s], bb[0], bb[1]);
                        mma16(S[st][jn * 2 + 1], qf[st][s], bb[2], bb[3]);
                    }
                }

            // p = exp2(S) packed fp16; P fragments in registers; l += P @ ones
            uint32_t pf[2][2][4];
#pragma unroll
            for (int st = 0; st < 2; st++)
#pragma unroll
                for (int t = 0; t < 2; t++) {
#pragma unroll
                    for (int u = 0; u < 2; u++) {
                        const float* Sv = S[st][2 * t + u];
                        __half2 e01 = h2exp2(__floats2half2_rn(Sv[0], Sv[1]));
                        __half2 e23 = h2exp2(__floats2half2_rn(Sv[2], Sv[3]));
                        pf[st][t][2 * u]     = *(uint32_t*)&e01;   // row r
                        pf[st][t][2 * u + 1] = *(uint32_t*)&e23;   // row r+8
                    }
                    mma16(lacc[st], pf[st][t], ONES, ONES);
                }

            // O(m32 x d64) += P @ V
#pragma unroll
            for (int t = 0; t < 2; t++)
#pragma unroll
                for (int j = 0; j < 4; j++) {
                    uint32_t bb[4];
                    ldsm4(bb, va + (uint32_t)(j * 16 * STRB) + (h * 32 + t * 16) * 2);
#pragma unroll
                    for (int st = 0; st < 2; st++) {
                        mma16(rO[st][2 * j],     pf[st][t], bb[0], bb[1]);
                        mma16(rO[st][2 * j + 1], pf[st][t], bb[2], bb[3]);
                    }
                }
        }
    }

    // epilogue: normalize, write g_ao [b][hw][c] fp16
    const int head = p & 7, gi = p >> 3;
#pragma unroll
    for (int st = 0; st < 2; st++) {
        const float i0 = 1.f / lacc[st][0], i1 = 1.f / lacc[st][2];
        const int row0 = m0 + wm * 32 + st * 16 + r, row1 = row0 + 8;
        const int v0 = row0 / HW, v1 = row1 / HW;
        __half* o0p = g_ao + ((gi * 4 + v0) * HW + (row0 - v0 * HW)) * CIN + head * 64;
        __half* o1p = g_ao + ((gi * 4 + v1) * HW + (row1 - v1 * HW)) * CIN + head * 64;
#pragma unroll
        for (int dt = 0; dt < 8; dt++) {
            *(__half2*)&o0p[dt * 8 + 2 * q] =
                __floats2half2_rn(rO[st][dt][0] * i0, rO[st][dt][1] * i0);
            *(__half2*)&o1p[dt * 8 + 2 * q] =
                __floats2half2_rn(rO[st][dt][2] * i1, rO[st][dt][3] * i1);
        }
    }
}

// ---------------------------------------------------------------------------
// Kernel C: proj + bias. D[m=o 128][n=hw 64] = W[o][c] @ AO[hw][c]^T.
// ---------------------------------------------------------------------------
__global__ __launch_bounds__(256, 3) void proj_mma(const float* __restrict__ bias,
                                                   float* __restrict__ out) {
    extern __shared__ __half smh[];
    const uint32_t sWb = s2u(smh);
    const uint32_t sBb = sWb + 2 * 9216 * 2;
    const int tid = threadIdx.x, wp = tid >> 5, lane = tid & 31;
    const int r = lane >> 2, q = lane & 3;
    const int wm = wp >> 1, wn = wp & 1;
    const int o0 = blockIdx.x * 128, hw0 = blockIdx.y * 64, b = blockIdx.z;
    const uint32_t aof = a_off16(lane, STRB), bof = b_off16(lane, STRB);

#define PRJ_PF(K0, BUF) {                                                       \
    _Pragma("unroll") for (int rr = 0; rr < 4; rr++) {                          \
        int f = tid + rr * 256, row = f >> 3, ch = (f & 7) * 8;                 \
        cpa16(sWb + (uint32_t)((BUF) * 9216 + row * 72 + ch) * 2u,              \
              g_wp + (o0 + row) * CIN + (K0) + ch);                             \
    }                                                                           \
    _Pragma("unroll") for (int rr = 0; rr < 2; rr++) {                          \
        int f = tid + rr * 256, row = f >> 3, ch = (f & 7) * 8;                 \
        cpa16(sBb + (uint32_t)((BUF) * 4608 + row * 72 + ch) * 2u,              \
              g_ao + ((b * HW) + hw0 + row) * CIN + (K0) + ch);                 \
    }                                                                           \
    cpcommit(); }

    PRJ_PF(0, 0);
    float acc[2][4][4] = {};

    for (int kk = 0; kk < 8; kk++) {
        const int buf = kk & 1;
        CPWAIT(0);
        __syncthreads();
        if (kk + 1 < 8) PRJ_PF((kk + 1) * 64, buf ^ 1);

        const uint32_t wa = sWb + (uint32_t)(buf * 9216 + wm * 32 * 72) * 2u + aof;
        const uint32_t xa = sBb + (uint32_t)(buf * 4608 + wn * 32 * 72) * 2u + bof;
#pragma unroll
        for (int s = 0; s < 4; s++) {
            uint32_t aW[2][4];
            ldsm4(aW[0], wa + s * 32);
            ldsm4(aW[1], wa + 16 * STRB + s * 32);
#pragma unroll
            for (int j2 = 0; j2 < 2; j2++) {
                uint32_t bb[4]; ldsm4(bb, xa + j2 * 16 * STRB + s * 32);
#pragma unroll
                for (int mi = 0; mi < 2; mi++) {
                    mma16(acc[mi][j2 * 2],     aW[mi], bb[0], bb[1]);
                    mma16(acc[mi][j2 * 2 + 1], aW[mi], bb[2], bb[3]);
                }
            }
        }
    }

#pragma unroll
    for (int mi = 0; mi < 2; mi++) {
        int o_r = o0 + wm * 32 + mi * 16 + r;
        float bv0 = bias[o_r], bv1 = bias[o_r + 8];
#pragma unroll
        for (int nj = 0; nj < 4; nj++) {
            int hw = hw0 + wn * 32 + nj * 8 + 2 * q;
            *(float2*)&out[(b * CIN + o_r) * HW + hw] =
                make_float2(acc[mi][nj][0] + bv0, acc[mi][nj][1] + bv0);
            *(float2*)&out[(b * CIN + o_r + 8) * HW + hw] =
                make_float2(acc[mi][nj][2] + bv1, acc[mi][nj][3] + bv1);
        }
    }
}

// ---------------------------------------------------------------------------
extern "C" void kernel_launch(void* const* d_in, const int* in_sizes, int n_in,
                              void* d_out, int out_size) {
    const float* x      = (const float*)d_in[0];
    const float* w_qkv  = (const float*)d_in[1];
    const float* w_proj = (const float*)d_in[2];
    const float* b_proj = (const float*)d_in[3];
    float* out = (float*)d_out;

    cudaFuncSetAttribute(qkv_mma,   cudaFuncAttributeMaxDynamicSharedMemorySize, 55296);
    cudaFuncSetAttribute(flash_mma, cudaFuncAttributeMaxDynamicSharedMemorySize, 73728);
    cudaFuncSetAttribute(proj_mma,  cudaFuncAttributeMaxDynamicSharedMemorySize, 55296);

    cvt_w<<<1024, 256>>>((const float4*)w_qkv, (const float4*)w_proj);
    tr_x<<<dim3(9, 8, 8), 256>>>(x);
    qkv_mma<<<dim3(9, 12, 8), 256, 55296>>>();
    flash_mma<<<dim3(18, 16), 128, 73728>>>();
    proj_mma<<<dim3(4, 9, 8), 256, 55296>>>(b_proj, out);
}

// round 8
// speedup vs baseline: 1.4448x; 1.0341x over previous
#include <cuda_runtime.h>
#include <cuda_fp16.h>
#include <cstdint>

#define HW     576
#define CIN    512
#define HD     64
#define NTOK   2304      // V_NUM * HW
#define NPAIR  16        // groups(2) * heads(8)
#define NB     8
#define QSCALE (0.125f * 1.4426950408889634f)   // hd^-0.5 * log2(e)
#define ONES   0x3C003C00u                       // half2(1.0, 1.0)

// Scratch (device globals: allocation-free rule). All fp16.
__device__ __align__(16) __half g_xt[NB * HW * CIN];     // x transposed [b][hw][c]
__device__ __align__(16) __half g_wq[3 * CIN * CIN];     // w_qkv [o][c]
__device__ __align__(16) __half g_wp[CIN * CIN];         // w_proj [o][c]
__device__ __align__(16) __half g_q[NPAIR * NTOK * HD];  // [p][n][d], scale folded
__device__ __align__(16) __half g_k[NPAIR * NTOK * HD];  // [p][n][d]
__device__ __align__(16) __half g_v[NPAIR * HD * NTOK];  // [p][d][n]
__device__ __align__(16) __half g_ao[NB * HW * CIN];     // attn out [b][hw][c]

// ---------------- helpers ----------------
__device__ __forceinline__ void mma16(float* c, const uint32_t* a, uint32_t b0, uint32_t b1) {
    asm("mma.sync.aligned.m16n8k16.row.col.f32.f16.f16.f32 "
        "{%0,%1,%2,%3}, {%4,%5,%6,%7}, {%8,%9}, {%0,%1,%2,%3};\n"
        : "+f"(c[0]), "+f"(c[1]), "+f"(c[2]), "+f"(c[3])
        : "r"(a[0]), "r"(a[1]), "r"(a[2]), "r"(a[3]), "r"(b0), "r"(b1));
}
// fp16 accumulate variant: D/C are 2 x .f16x2 regs (half2 row r, half2 row r+8)
__device__ __forceinline__ void mma16h(uint32_t* c, const uint32_t* a, uint32_t b0, uint32_t b1) {
    asm("mma.sync.aligned.m16n8k16.row.col.f16.f16.f16.f16 "
        "{%0,%1}, {%2,%3,%4,%5}, {%6,%7}, {%0,%1};\n"
        : "+r"(c[0]), "+r"(c[1])
        : "r"(a[0]), "r"(a[1]), "r"(a[2]), "r"(a[3]), "r"(b0), "r"(b1));
}
__device__ __forceinline__ void ldsm4(uint32_t* d, uint32_t a) {
    asm volatile("ldmatrix.sync.aligned.m8n8.x4.shared.b16 {%0,%1,%2,%3}, [%4];\n"
        : "=r"(d[0]), "=r"(d[1]), "=r"(d[2]), "=r"(d[3]) : "r"(a));
}
__device__ __forceinline__ uint32_t s2u(const void* p) {
    return (uint32_t)__cvta_generic_to_shared(p);
}
__device__ __forceinline__ void cpa16(uint32_t dst, const void* src) {
    asm volatile("cp.async.cg.shared.global [%0], [%1], 16;\n" :: "r"(dst), "l"(src));
}
__device__ __forceinline__ void cpcommit() {
    asm volatile("cp.async.commit_group;\n" ::: "memory");
}
#define CPWAIT(n) asm volatile("cp.async.wait_group %0;\n" :: "n"(n) : "memory")

// fp16 LDSM lane offsets (bytes). strideB = row stride in bytes.
__device__ __forceinline__ uint32_t a_off16(int lane, int strideB) {
    return (uint32_t)(((lane & 7) + ((lane >> 3) & 1) * 8) * strideB + (lane >> 4) * 16);
}
__device__ __forceinline__ uint32_t b_off16(int lane, int strideB) {
    return (uint32_t)(((lane & 7) + ((lane >> 4) & 1) * 8) * strideB + ((lane >> 3) & 1) * 16);
}

#define STRB 144      // 72 halves per smem row

// ---------------------------------------------------------------------------
// Prologue 1: convert weights to fp16.
// ---------------------------------------------------------------------------
__global__ __launch_bounds__(256) void cvt_w(const float4* __restrict__ wq,
                                             const float4* __restrict__ wp) {
    int i = blockIdx.x * 256 + threadIdx.x;
    float4 v; __half* dst;
    if (i < 196608) { v = wq[i];          dst = g_wq + i * 4; }
    else            { v = wp[i - 196608]; dst = g_wp + (i - 196608) * 4; }
    *(__half2*)dst       = __floats2half2_rn(v.x, v.y);
    *(__half2*)(dst + 2) = __floats2half2_rn(v.z, v.w);
}

// ---------------------------------------------------------------------------
// Prologue 2: transpose+convert x [b][c][hw] -> g_xt [b][hw][c] fp16.
// ---------------------------------------------------------------------------
__global__ __launch_bounds__(256) void tr_x(const float* __restrict__ x) {
    __shared__ float sT[64 * 65];
    const int tid = threadIdx.x;
    const int hw0 = blockIdx.x * 64, c0 = blockIdx.y * 64, b = blockIdx.z;
#pragma unroll
    for (int rr = 0; rr < 4; rr++) {
        int f = tid + rr * 256, row = f >> 4, h4 = (f & 15) * 4;
        float4 v = *(const float4*)&x[((b * CIN) + c0 + row) * HW + hw0 + h4];
        sT[row * 65 + h4 + 0] = v.x; sT[row * 65 + h4 + 1] = v.y;
        sT[row * 65 + h4 + 2] = v.z; sT[row * 65 + h4 + 3] = v.w;
    }
    __syncthreads();
    {
        int f = tid, hwr = f >> 2, cc = (f & 3) * 16;
        __half* dst = g_xt + ((b * HW) + hw0 + hwr) * CIN + c0 + cc;
#pragma unroll
        for (int j = 0; j < 8; j++)
            *(__half2*)(dst + 2 * j) =
                __floats2half2_rn(sT[(cc + 2 * j) * 65 + hwr], sT[(cc + 2 * j + 1) * 65 + hwr]);
    }
}

// ---------------------------------------------------------------------------
// Kernel A: QKV. D[m=hw 64][n=o 128] = X[hw][c] @ W[o][c]^T, K=512, BK=64.
// ---------------------------------------------------------------------------
__global__ __launch_bounds__(256, 3) void qkv_mma() {
    extern __shared__ __half smh[];
    const uint32_t sXb = s2u(smh);
    const uint32_t sWb = sXb + 2 * 4608 * 2;
    const int tid = threadIdx.x, wp = tid >> 5, lane = tid & 31;
    const int r = lane >> 2, q = lane & 3;
    const int wm = wp >> 2, wn = wp & 3;
    const int hw0 = blockIdx.x * 64, o0 = blockIdx.y * 128, b = blockIdx.z;
    const uint32_t aof = a_off16(lane, STRB), bof = b_off16(lane, STRB);

#define QKV_PF(K0, BUF) {                                                       \
    _Pragma("unroll") for (int rr = 0; rr < 2; rr++) {                          \
        int f = tid + rr * 256, row = f >> 3, ch = (f & 7) * 8;                 \
        cpa16(sXb + (uint32_t)((BUF) * 4608 + row * 72 + ch) * 2u,              \
              g_xt + ((b * HW) + hw0 + row) * CIN + (K0) + ch);                 \
    }                                                                           \
    _Pragma("unroll") for (int rr = 0; rr < 4; rr++) {                          \
        int f = tid + rr * 256, row = f >> 3, ch = (f & 7) * 8;                 \
        cpa16(sWb + (uint32_t)((BUF) * 9216 + row * 72 + ch) * 2u,              \
              g_wq + (o0 + row) * CIN + (K0) + ch);                             \
    }                                                                           \
    cpcommit(); }

    QKV_PF(0, 0);
    float acc[2][4][4] = {};

    for (int kk = 0; kk < 8; kk++) {
        const int buf = kk & 1;
        CPWAIT(0);
        __syncthreads();
        if (kk + 1 < 8) QKV_PF((kk + 1) * 64, buf ^ 1);

        const uint32_t xa = sXb + (uint32_t)(buf * 4608 + wm * 32 * 72) * 2u + aof;
        const uint32_t wa = sWb + (uint32_t)(buf * 9216 + wn * 32 * 72) * 2u + bof;
#pragma unroll
        for (int s = 0; s < 4; s++) {
            uint32_t aX[2][4];
            ldsm4(aX[0], xa + s * 32);
            ldsm4(aX[1], xa + 16 * STRB + s * 32);
#pragma unroll
            for (int j2 = 0; j2 < 2; j2++) {
                uint32_t bb[4]; ldsm4(bb, wa + j2 * 16 * STRB + s * 32);
#pragma unroll
                for (int mi = 0; mi < 2; mi++) {
                    mma16(acc[mi][j2 * 2],     aX[mi], bb[0], bb[1]);
                    mma16(acc[mi][j2 * 2 + 1], aX[mi], bb[2], bb[3]);
                }
            }
        }
    }

    const int g2 = b >> 2, vv = b & 3;
#pragma unroll
    for (int mi = 0; mi < 2; mi++) {
        int hwr = hw0 + wm * 32 + mi * 16 + r;
        int n0t = vv * HW + hwr, n1t = n0t + 8;
#pragma unroll
        for (int nj = 0; nj < 4; nj++) {
            int o = o0 + wn * 32 + nj * 8 + 2 * q;
            int head = o / 192, rem = o - head * 192, which = rem >> 6, d = rem & 63;
            int pp = g2 * 8 + head;
            float c0 = acc[mi][nj][0], c1 = acc[mi][nj][1];
            float c2 = acc[mi][nj][2], c3 = acc[mi][nj][3];
            if (which == 0) {
                *(__half2*)&g_q[(pp * NTOK + n0t) * HD + d] = __floats2half2_rn(c0 * QSCALE, c1 * QSCALE);
                *(__half2*)&g_q[(pp * NTOK + n1t) * HD + d] = __floats2half2_rn(c2 * QSCALE, c3 * QSCALE);
            } else if (which == 1) {
                *(__half2*)&g_k[(pp * NTOK + n0t) * HD + d] = __floats2half2_rn(c0, c1);
                *(__half2*)&g_k[(pp * NTOK + n1t) * HD + d] = __floats2half2_rn(c2, c3);
            } else {
                g_v[(pp * HD + d) * NTOK + n0t]     = __float2half_rn(c0);
                g_v[(pp * HD + d + 1) * NTOK + n0t] = __float2half_rn(c1);
                g_v[(pp * HD + d) * NTOK + n1t]     = __float2half_rn(c2);
                g_v[(pp * HD + d + 1) * NTOK + n1t] = __float2half_rn(c3);
            }
        }
    }
}

// ---------------------------------------------------------------------------
// Kernel B: flash attention fp16, FA2-style: 4 warps x m32 strips, BM=128.
// S accumulated in fp16 (D-frag == packed exp2 input == P A-frag);
// n in two 32-halves; P register-resident; row sums via ones-mma (fp32).
// grid (18, 16), 128 thr, 3-stage cp.async ring.
// ---------------------------------------------------------------------------
__global__ __launch_bounds__(128, 2) void flash_mma() {
    extern __shared__ __half smh[];
    const uint32_t sQb = s2u(smh);
    const uint32_t sKb = sQb + 128 * 72 * 2;
    const uint32_t sVb = sKb + 3 * 4608 * 2;

    const int tid = threadIdx.x, wm = tid >> 5, lane = tid & 31;
    const int r = lane >> 2, q = lane & 3;
    const int p = blockIdx.y, m0 = blockIdx.x * 128;

    const __half* Qb = g_q + (p * NTOK + m0) * HD;
    const __half* Kb = g_k + p * NTOK * HD;
    const __half* Vb = g_v + p * HD * NTOK;

    const uint32_t aof = a_off16(lane, STRB), bof = b_off16(lane, STRB);

#define FL_PF(N0, BUF) {                                                        \
    _Pragma("unroll") for (int rr = 0; rr < 4; rr++) {                          \
        int f = tid + rr * 128, row = f >> 3, ch = (f & 7) * 8;                 \
        cpa16(sKb + (uint32_t)((BUF) * 4608 + row * 72 + ch) * 2u,              \
              Kb + ((N0) + row) * HD + ch);                                     \
        cpa16(sVb + (uint32_t)((BUF) * 4608 + row * 72 + ch) * 2u,              \
              Vb + row * NTOK + (N0) + ch);                                     \
    }                                                                           \
    cpcommit(); }

    // stage Q (128 rows x 64 halves), then first two K/V stages
#pragma unroll
    for (int rr = 0; rr < 8; rr++) {
        int f = tid + rr * 128, row = f >> 3, ch = (f & 7) * 8;
        cpa16(sQb + (uint32_t)(row * 72 + ch) * 2u, Qb + row * HD + ch);
    }
    cpcommit();
    FL_PF(0, 0);
    FL_PF(64, 1);

    CPWAIT(1);            // Q + stage0 ready
    __syncthreads();
    uint32_t qf[2][4][4];
#pragma unroll
    for (int st = 0; st < 2; st++) {
        const uint32_t qa = sQb + (uint32_t)((wm * 32 + st * 16) * 72) * 2u + aof;
#pragma unroll
        for (int s = 0; s < 4; s++) ldsm4(qf[st][s], qa + s * 32);
    }

    float rO[2][8][4] = {};     // [strip][d-tile][4]
    float lacc[2][4] = {};      // row sums via ones-mma (fp32 acc)

    for (int it = 0; it < 36; it++) {
        const int buf = it % 3;
        if (it) { CPWAIT(1); __syncthreads(); }
        if (it + 2 < 36) FL_PF((it + 2) * 64, (it + 2) % 3);

        const uint32_t ka = sKb + (uint32_t)(buf * 4608) * 2u + bof;
        const uint32_t va = sVb + (uint32_t)(buf * 4608) * 2u + bof;

#pragma unroll
        for (int h = 0; h < 2; h++) {     // n in two 32-halves
            // S(m32 x n32) = Q K^T, fp16 accumulate.
            // Sh[st][nt] = {half2 row r, half2 row r+8} at cols nt*8+2q.
            uint32_t Sh[2][4][2] = {};
#pragma unroll
            for (int s = 0; s < 4; s++)
#pragma unroll
                for (int jn = 0; jn < 2; jn++) {
                    uint32_t bb[4];
                    ldsm4(bb, ka + (uint32_t)((h * 32 + jn * 16) * STRB) + s * 32);
#pragma unroll
                    for (int st = 0; st < 2; st++) {
                        mma16h(Sh[st][jn * 2],     qf[st][s], bb[0], bb[1]);
                        mma16h(Sh[st][jn * 2 + 1], qf[st][s], bb[2], bb[3]);
                    }
                }

            // p = exp2(S): fp16x2 exp directly on mma output regs.
            // P A-frag (k-tile t): {S[2t].row_r, S[2t].row_r8, S[2t+1].row_r, S[2t+1].row_r8}
            uint32_t pf[2][2][4];
#pragma unroll
            for (int st = 0; st < 2; st++)
#pragma unroll
                for (int t = 0; t < 2; t++) {
                    __half2 e0 = h2exp2(*(__half2*)&Sh[st][2 * t][0]);
                    __half2 e1 = h2exp2(*(__half2*)&Sh[st][2 * t][1]);
                    __half2 e2 = h2exp2(*(__half2*)&Sh[st][2 * t + 1][0]);
                    __half2 e3 = h2exp2(*(__half2*)&Sh[st][2 * t + 1][1]);
                    pf[st][t][0] = *(uint32_t*)&e0;
                    pf[st][t][1] = *(uint32_t*)&e1;
                    pf[st][t][2] = *(uint32_t*)&e2;
                    pf[st][t][3] = *(uint32_t*)&e3;
                    mma16(lacc[st], pf[st][t], ONES, ONES);
                }

            // O(m32 x d64) += P @ V
#pragma unroll
            for (int t = 0; t < 2; t++)
#pragma unroll
                for (int j = 0; j < 4; j++) {
                    uint32_t bb[4];
                    ldsm4(bb, va + (uint32_t)(j * 16 * STRB) + (h * 32 + t * 16) * 2);
#pragma unroll
                    for (int st = 0; st < 2; st++) {
                        mma16(rO[st][2 * j],     pf[st][t], bb[0], bb[1]);
                        mma16(rO[st][2 * j + 1], pf[st][t], bb[2], bb[3]);
                    }
                }
        }
    }

    // epilogue: normalize, write g_ao [b][hw][c] fp16
    const int head = p & 7, gi = p >> 3;
#pragma unroll
    for (int st = 0; st < 2; st++) {
        const float i0 = 1.f / lacc[st][0], i1 = 1.f / lacc[st][2];
        const int row0 = m0 + wm * 32 + st * 16 + r, row1 = row0 + 8;
        const int v0 = row0 / HW, v1 = row1 / HW;
        __half* o0p = g_ao + ((gi * 4 + v0) * HW + (row0 - v0 * HW)) * CIN + head * 64;
        __half* o1p = g_ao + ((gi * 4 + v1) * HW + (row1 - v1 * HW)) * CIN + head * 64;
#pragma unroll
        for (int dt = 0; dt < 8; dt++) {
            *(__half2*)&o0p[dt * 8 + 2 * q] =
                __floats2half2_rn(rO[st][dt][0] * i0, rO[st][dt][1] * i0);
            *(__half2*)&o1p[dt * 8 + 2 * q] =
                __floats2half2_rn(rO[st][dt][2] * i1, rO[st][dt][3] * i1);
        }
    }
}

// ---------------------------------------------------------------------------
// Kernel C: proj + bias. D[m=o 128][n=hw 64] = W[o][c] @ AO[hw][c]^T.
// ---------------------------------------------------------------------------
__global__ __launch_bounds__(256, 3) void proj_mma(const float* __restrict__ bias,
                                                   float* __restrict__ out) {
    extern __shared__ __half smh[];
    const uint32_t sWb = s2u(smh);
    const uint32_t sBb = sWb + 2 * 9216 * 2;
    const int tid = threadIdx.x, wp = tid >> 5, lane = tid & 31;
    const int r = lane >> 2, q = lane & 3;
    const int wm = wp >> 1, wn = wp & 1;
    const int o0 = blockIdx.x * 128, hw0 = blockIdx.y * 64, b = blockIdx.z;
    const uint32_t aof = a_off16(lane, STRB), bof = b_off16(lane, STRB);

#define PRJ_PF(K0, BUF) {                                                       \
    _Pragma("unroll") for (int rr = 0; rr < 4; rr++) {                          \
        int f = tid + rr * 256, row = f >> 3, ch = (f & 7) * 8;                 \
        cpa16(sWb + (uint32_t)((BUF) * 9216 + row * 72 + ch) * 2u,              \
              g_wp + (o0 + row) * CIN + (K0) + ch);                             \
    }                                                                           \
    _Pragma("unroll") for (int rr = 0; rr < 2; rr++) {                          \
        int f = tid + rr * 256, row = f >> 3, ch = (f & 7) * 8;                 \
        cpa16(sBb + (uint32_t)((BUF) * 4608 + row * 72 + ch) * 2u,              \
              g_ao + ((b * HW) + hw0 + row) * CIN + (K0) + ch);                 \
    }                                                                           \
    cpcommit(); }

    PRJ_PF(0, 0);
    float acc[2][4][4] = {};

    for (int kk = 0; kk < 8; kk++) {
        const int buf = kk & 1;
        CPWAIT(0);
        __syncthreads();
        if (kk + 1 < 8) PRJ_PF((kk + 1) * 64, buf ^ 1);

        const uint32_t wa = sWb + (uint32_t)(buf * 9216 + wm * 32 * 72) * 2u + aof;
        const uint32_t xa = sBb + (uint32_t)(buf * 4608 + wn * 32 * 72) * 2u + bof;
#pragma unroll
        for (int s = 0; s < 4; s++) {
            uint32_t aW[2][4];
            ldsm4(aW[0], wa + s * 32);
            ldsm4(aW[1], wa + 16 * STRB + s * 32);
#pragma unroll
            for (int j2 = 0; j2 < 2; j2++) {
                uint32_t bb[4]; ldsm4(bb, xa + j2 * 16 * STRB + s * 32);
#pragma unroll
                for (int mi = 0; mi < 2; mi++) {
                    mma16(acc[mi][j2 * 2],     aW[mi], bb[0], bb[1]);
                    mma16(acc[mi][j2 * 2 + 1], aW[mi], bb[2], bb[3]);
                }
            }
        }
    }

#pragma unroll
    for (int mi = 0; mi < 2; mi++) {
        int o_r = o0 + wm * 32 + mi * 16 + r;
        float bv0 = bias[o_r], bv1 = bias[o_r + 8];
#pragma unroll
        for (int nj = 0; nj < 4; nj++) {
            int hw = hw0 + wn * 32 + nj * 8 + 2 * q;
            *(float2*)&out[(b * CIN + o_r) * HW + hw] =
                make_float2(acc[mi][nj][0] + bv0, acc[mi][nj][1] + bv0);
            *(float2*)&out[(b * CIN + o_r + 8) * HW + hw] =
                make_float2(acc[mi][nj][2] + bv1, acc[mi][nj][3] + bv1);
        }
    }
}

// ---------------------------------------------------------------------------
extern "C" void kernel_launch(void* const* d_in, const int* in_sizes, int n_in,
                              void* d_out, int out_size) {
    const float* x      = (const float*)d_in[0];
    const float* w_qkv  = (const float*)d_in[1];
    const float* w_proj = (const float*)d_in[2];
    const float* b_proj = (const float*)d_in[3];
    float* out = (float*)d_out;

    cudaFuncSetAttribute(qkv_mma,   cudaFuncAttributeMaxDynamicSharedMemorySize, 55296);
    cudaFuncSetAttribute(flash_mma, cudaFuncAttributeMaxDynamicSharedMemorySize, 73728);
    cudaFuncSetAttribute(proj_mma,  cudaFuncAttributeMaxDynamicSharedMemorySize, 55296);

    cvt_w<<<1024, 256>>>((const float4*)w_qkv, (const float4*)w_proj);
    tr_x<<<dim3(9, 8, 8), 256>>>(x);
    qkv_mma<<<dim3(9, 12, 8), 256, 55296>>>();
    flash_mma<<<dim3(18, 16), 128, 73728>>>();
    proj_mma<<<dim3(4, 9, 8), 256, 55296>>>(b_proj, out);
}